// round 6
// baseline (speedup 1.0000x reference)
#include <cuda_runtime.h>

#define TS   16     // samples per block
#define NT   512    // threads per block (16 warps)
#define NBLK 128    // 2048 / TS

__constant__ int c_FOFF[9] = {0,100000,150000,150010,150013,150113,150163,151163,151187};
__constant__ int c_EDIM[9] = {16,16,8,4,8,8,8,4,4};
__constant__ int c_EOFF[9] = {0,16,32,40,44,52,60,68,72};
#define NF_LAST 151192

struct P30 { const void* p[30]; };
typedef unsigned long long u64;

__device__ __forceinline__ void ffma2(u64 &d, u64 a, u64 b) {
    asm("fma.rn.f32x2 %0, %1, %2, %0;" : "+l"(d) : "l"(a), "l"(b));
}
__device__ __forceinline__ void fadd2(u64 &d, u64 a) {
    asm("add.rn.f32x2 %0, %0, %1;" : "+l"(d) : "l"(a));
}
__device__ __forceinline__ u64 pack2(float x) {
    u64 r; asm("mov.b64 %0, {%1, %1};" : "=l"(r) : "f"(x)); return r;
}
__device__ __forceinline__ float2 unpack2(u64 v) {
    float2 f; asm("mov.b64 {%0, %1}, %2;" : "=f"(f.x), "=f"(f.y) : "l"(v)); return f;
}
__device__ __forceinline__ u64 d2u(double d) { return __double_as_longlong(d); }
__device__ __forceinline__ int read_id(const void* p, int i, bool is64) {
    return is64 ? (int)((const long long*)p)[i] : ((const int*)p)[i];
}

// row strides (in u64) padded 16->18 to avoid 128B-stride bank conflicts
#define RS 18
// float offsets into dynamic smem
#define OFF_XT    0          // u64[77][18]   dup X     (2772 floats)
#define OFF_H1    2772       // u64[256][18]  dup H1    (9216 floats)
#define OFF_H2    11988      // u64[128][18]  dup H2    (4608 floats)
#define OFF_P2    16596      // u64[4*64][18] L2 partials (9216 floats)
#define OFF_P3    25812      // u64[4*32][18] L3 partials (4608 floats)
#define OFF_H3    30420      // float[64][17] H3        (1088 floats)
#define OFF_BASE  31508
#define OFF_PRICE 31524
#define OFF_IDX   31540      // int[144]
#define SMEM_FLOATS 31684
#define SMEM_BYTES  (SMEM_FLOATS * 4)

extern "C" __global__ void __launch_bounds__(NT, 1)
deepfm_kernel(P30 a, float* __restrict__ out, int B)
{
    extern __shared__ __align__(16) float sm[];
    u64*   sXTd   = (u64*)(sm + OFF_XT);
    u64*   sH1d   = (u64*)(sm + OFF_H1);
    u64*   sH2d   = (u64*)(sm + OFF_H2);
    u64*   sP2    = (u64*)(sm + OFF_P2);
    u64*   sP3    = (u64*)(sm + OFF_P3);
    float* sH3    = sm + OFF_H3;
    float* sBase  = sm + OFF_BASE;
    float* sPrice = sm + OFF_PRICE;
    int*   sIdx   = (int*)(sm + OFF_IDX);

    const int t  = threadIdx.x;
    const int w  = t >> 5;
    const int ln = t & 31;
    const int s0blk = blockIdx.x * TS;

    // ---- input-layout detection (deterministic, data-driven) ----
    const u64* u0 = (const u64*)a.p[0];
    const bool is64 = ((u0[0] | u0[1] | u0[2] | u0[3]) < (1ULL << 20));
    const u64* u7 = (const u64*)a.p[7];
    const bool dict = (u7[0] < (1ULL << 40));

    const void* idp[9];
    #pragma unroll
    for (int f = 0; f < 7; f++) idp[f] = a.p[f];
    const float* price;
    if (dict) { idp[7] = a.p[7]; idp[8] = a.p[8]; price = (const float*)a.p[9]; }
    else      { price = (const float*)a.p[7]; idp[7] = a.p[8]; idp[8] = a.p[9]; }

    const float* emb[9];
    #pragma unroll
    for (int f = 0; f < 9; f++) emb[f] = (const float*)a.p[10 + f];
    const float* __restrict__ w_dense = (const float*)a.p[19];
    const float* __restrict__ b_dense = (const float*)a.p[20];
    const float* __restrict__ fm_v    = (const float*)a.p[21];
    const float* __restrict__ W1 = (const float*)a.p[22];
    const float* __restrict__ b1 = (const float*)a.p[23];
    const float* __restrict__ W2 = (const float*)a.p[24];
    const float* __restrict__ b2 = (const float*)a.p[25];
    const float* __restrict__ W3 = (const float*)a.p[26];
    const float* __restrict__ b3 = (const float*)a.p[27];
    const float* __restrict__ Wo = (const float*)a.p[28];
    const float* __restrict__ bo = (const float*)a.p[29];

    // ---- gather ids + price ----
    if (t < TS * 9) {
        int s = t / 9, f = t - s * 9;
        sIdx[s * 9 + f] = read_id(idp[f], s0blk + s, is64);
    }
    if (t >= 160 && t < 160 + TS) sPrice[t - 160] = price[s0blk + (t - 160)];
    __syncthreads();

    // ---- warps 0-7: FM + dense; warps 8-15: build duplicated XT[77][16] ----
    if (w < 8) {
        int s = w * 2 + (ln >> 4);
        int e = ln & 15;
        float pv = sPrice[s] * 1e-3f;
        float fs = 0.f, ss = 0.f;
        #pragma unroll
        for (int f = 0; f < 9; f++) {
            int row = c_FOFF[f] + sIdx[s * 9 + f];
            float v = fm_v[row * 16 + e];
            fs += v; ss += v * v;
        }
        {
            float v = fm_v[NF_LAST * 16 + e];
            fs += pv * v; ss += pv * pv * v * v;
        }
        float val = fs * fs - ss;
        #pragma unroll
        for (int o = 8; o; o >>= 1) val += __shfl_xor_sync(0xffffffffu, val, o, 16);
        float fm = 0.5f * val;

        float dn = 0.f;
        if (e < 9)  dn = w_dense[c_FOFF[e] + sIdx[s * 9 + e]];
        if (e == 9) dn = pv * w_dense[NF_LAST];
        #pragma unroll
        for (int o = 8; o; o >>= 1) dn += __shfl_xor_sync(0xffffffffu, dn, o, 16);

        if (e == 0) sBase[s] = fm + dn + b_dense[0];
    } else {
        for (int idx = t - 256; idx < TS * 77; idx += 256) {
            int s = idx & 15, c = idx >> 4;
            float v;
            if (c == 76) v = sPrice[s];
            else {
                int f = 8;
                #pragma unroll
                for (int k = 8; k >= 1; k--) if (c < c_EOFF[k]) f = k - 1;
                v = emb[f][sIdx[s * 9 + f] * c_EDIM[f] + (c - c_EOFF[f])];
            }
            sXTd[c * RS + s] = pack2(v);
        }
    }
    __syncthreads();

    // ---- Layer 1: K=77, N=256, 16 warps. acc = (j,j+1) pair x 4 samples. ----
    {
        int jql = ln & 7, sg = ln >> 3;
        int j0 = (w * 8 + jql) * 2;        // 0..254
        int s0 = sg * 4;
        u64 bia = *(const u64*)(b1 + j0);
        u64 ac0 = bia, ac1 = bia, ac2 = bia, ac3 = bia;
        #pragma unroll 7
        for (int i = 0; i < 77; i++) {
            u64 wv = *(const u64*)(W1 + i * 256 + j0);   // (w_j0, w_j1)
            double2 xa = *(const double2*)(sXTd + i * RS + s0);
            double2 xb = *(const double2*)(sXTd + i * RS + s0 + 2);
            ffma2(ac0, wv, d2u(xa.x)); ffma2(ac1, wv, d2u(xa.y));
            ffma2(ac2, wv, d2u(xb.x)); ffma2(ac3, wv, d2u(xb.y));
        }
        float2 f0 = unpack2(ac0), f1 = unpack2(ac1), f2 = unpack2(ac2), f3 = unpack2(ac3);
        float r0[4] = {fmaxf(f0.x,0.f), fmaxf(f1.x,0.f), fmaxf(f2.x,0.f), fmaxf(f3.x,0.f)};
        float r1[4] = {fmaxf(f0.y,0.f), fmaxf(f1.y,0.f), fmaxf(f2.y,0.f), fmaxf(f3.y,0.f)};
        float4* d0 = (float4*)(sH1d + j0 * RS + s0);
        float4* d1 = (float4*)(sH1d + (j0 + 1) * RS + s0);
        d0[0] = make_float4(r0[0], r0[0], r0[1], r0[1]);
        d0[1] = make_float4(r0[2], r0[2], r0[3], r0[3]);
        d1[0] = make_float4(r1[0], r1[0], r1[1], r1[1]);
        d1[1] = make_float4(r1[2], r1[2], r1[3], r1[3]);
    }
    __syncthreads();

    // ---- Layer 2: K=256 split-K x4, N=128, 16 warps. Direct LDG W2. ----
    {
        int ks = w & 3, jg = w >> 2;
        int jql = ln & 7, sg = ln >> 3;
        int j0 = jg * 32 + jql * 4;        // 0..124, step 4
        int s0 = sg * 4;
        u64 aA0=0,aA1=0,aA2=0,aA3=0, aB0=0,aB1=0,aB2=0,aB3=0;
        const float* Wp = W2 + ks * 64 * 128 + j0;
        const u64*   Xp = sH1d + ks * 64 * RS + s0;
        #pragma unroll 8
        for (int ii = 0; ii < 64; ii++) {
            double2 wd = *(const double2*)(Wp + ii * 128);
            u64 w01 = d2u(wd.x), w23 = d2u(wd.y);
            double2 xa = *(const double2*)(Xp + ii * RS);
            double2 xb = *(const double2*)(Xp + ii * RS + 2);
            u64 x0 = d2u(xa.x), x1 = d2u(xa.y), x2 = d2u(xb.x), x3 = d2u(xb.y);
            ffma2(aA0, w01, x0); ffma2(aA1, w01, x1); ffma2(aA2, w01, x2); ffma2(aA3, w01, x3);
            ffma2(aB0, w23, x0); ffma2(aB1, w23, x1); ffma2(aB2, w23, x2); ffma2(aB3, w23, x3);
        }
        int jp0 = j0 >> 1;                 // 0..62, step 2
        u64* pA = sP2 + (ks * 64 + jp0) * RS + s0;
        u64* pB = sP2 + (ks * 64 + jp0 + 1) * RS + s0;
        ((double2*)pA)[0] = make_double2(__longlong_as_double(aA0), __longlong_as_double(aA1));
        ((double2*)pA)[1] = make_double2(__longlong_as_double(aA2), __longlong_as_double(aA3));
        ((double2*)pB)[0] = make_double2(__longlong_as_double(aB0), __longlong_as_double(aB1));
        ((double2*)pB)[1] = make_double2(__longlong_as_double(aB2), __longlong_as_double(aB3));
    }
    __syncthreads();

    // ---- L2 reduce + bias + relu -> duplicated H2 ----
    {
        int jp = t >> 3;                   // 0..63
        int sp = (t & 7) * 2;              // samples sp, sp+1
        double2 v0 = *(const double2*)(sP2 + (jp)           * RS + sp);
        double2 v1 = *(const double2*)(sP2 + (64  + jp)     * RS + sp);
        double2 v2 = *(const double2*)(sP2 + (128 + jp)     * RS + sp);
        double2 v3 = *(const double2*)(sP2 + (192 + jp)     * RS + sp);
        u64 sA = d2u(v0.x), sB = d2u(v0.y);
        fadd2(sA, d2u(v1.x)); fadd2(sB, d2u(v1.y));
        fadd2(sA, d2u(v2.x)); fadd2(sB, d2u(v2.y));
        fadd2(sA, d2u(v3.x)); fadd2(sB, d2u(v3.y));
        u64 bb = *(const u64*)(b2 + jp * 2);
        fadd2(sA, bb); fadd2(sB, bb);
        float2 fa = unpack2(sA), fb = unpack2(sB);
        float a0 = fmaxf(fa.x, 0.f), a1 = fmaxf(fa.y, 0.f);
        float c0 = fmaxf(fb.x, 0.f), c1 = fmaxf(fb.y, 0.f);
        *(float4*)(sH2d + (2 * jp)     * RS + sp) = make_float4(a0, a0, c0, c0);
        *(float4*)(sH2d + (2 * jp + 1) * RS + sp) = make_float4(a1, a1, c1, c1);
    }
    __syncthreads();

    // ---- Layer 3: K=128 split-K x4, N=64, 16 warps. Direct LDG W3. ----
    {
        int ks = w & 3, jg = w >> 2;
        int jql = ln & 7, sg = ln >> 3;
        int j0 = jg * 16 + jql * 2;        // 0..62, step 2
        int s0 = sg * 4;
        u64 a0=0, a1=0, a2=0, a3=0;
        const float* Wp = W3 + ks * 32 * 64 + j0;
        const u64*   Xp = sH2d + ks * 32 * RS + s0;
        #pragma unroll 8
        for (int ii = 0; ii < 32; ii++) {
            u64 wv = *(const u64*)(Wp + ii * 64);
            double2 xa = *(const double2*)(Xp + ii * RS);
            double2 xb = *(const double2*)(Xp + ii * RS + 2);
            ffma2(a0, wv, d2u(xa.x)); ffma2(a1, wv, d2u(xa.y));
            ffma2(a2, wv, d2u(xb.x)); ffma2(a3, wv, d2u(xb.y));
        }
        int jp = j0 >> 1;                  // 0..31
        u64* pP = sP3 + (ks * 32 + jp) * RS + s0;
        ((double2*)pP)[0] = make_double2(__longlong_as_double(a0), __longlong_as_double(a1));
        ((double2*)pP)[1] = make_double2(__longlong_as_double(a2), __longlong_as_double(a3));
    }
    __syncthreads();

    // ---- L3 reduce + bias + relu -> H3[64][17] ----
    {
        int jp = t >> 4;                   // 0..31
        int s  = t & 15;
        u64 v = sP3[jp * RS + s];
        fadd2(v, sP3[(32 + jp) * RS + s]);
        fadd2(v, sP3[(64 + jp) * RS + s]);
        fadd2(v, sP3[(96 + jp) * RS + s]);
        u64 bb = *(const u64*)(b3 + jp * 2);
        fadd2(v, bb);
        float2 f = unpack2(v);
        sH3[(2 * jp)     * 17 + s] = fmaxf(f.x, 0.f);
        sH3[(2 * jp + 1) * 17 + s] = fmaxf(f.y, 0.f);
    }
    __syncthreads();

    // ---- Output: warps 0-3, 8 lanes per sample ----
    if (w < 4) {
        int s  = w * 4 + (ln >> 3);
        int q8 = ln & 7;
        float v = 0.f;
        #pragma unroll
        for (int q = 0; q < 8; q++)
            v += sH3[(q8 * 8 + q) * 17 + s] * Wo[q8 * 8 + q];
        v += __shfl_xor_sync(0xffffffffu, v, 4, 8);
        v += __shfl_xor_sync(0xffffffffu, v, 2, 8);
        v += __shfl_xor_sync(0xffffffffu, v, 1, 8);
        if (q8 == 0 && s0blk + s < B)
            out[s0blk + s] = v + bo[0] + sBase[s];
    }
}

extern "C" void kernel_launch(void* const* d_in, const int* in_sizes, int n_in,
                              void* d_out, int out_size)
{
    (void)in_sizes; (void)n_in;
    P30 a;
    for (int i = 0; i < 30; i++) a.p[i] = d_in[i];
    cudaFuncSetAttribute(deepfm_kernel, cudaFuncAttributeMaxDynamicSharedMemorySize, SMEM_BYTES);
    deepfm_kernel<<<NBLK, NT, SMEM_BYTES>>>(a, (float*)d_out, out_size);
}

// round 7
// speedup vs baseline: 1.0700x; 1.0700x over previous
#include <cuda_runtime.h>

#define TS   8      // samples per block
#define NT   256    // threads per block (8 warps)
#define NBLK 256    // 2048 / TS

__constant__ int c_FOFF[9] = {0,100000,150000,150010,150013,150113,150163,151163,151187};
__constant__ int c_EDIM[9] = {16,16,8,4,8,8,8,4,4};
__constant__ int c_EOFF[9] = {0,16,32,40,44,52,60,68,72};
#define NF_LAST 151192

struct P30 { const void* p[30]; };
typedef unsigned long long u64;

__device__ __forceinline__ void ffma2(u64 &d, u64 a, u64 b) {
    asm("fma.rn.f32x2 %0, %1, %2, %0;" : "+l"(d) : "l"(a), "l"(b));
}
__device__ __forceinline__ void fadd2(u64 &d, u64 a) {
    asm("add.rn.f32x2 %0, %0, %1;" : "+l"(d) : "l"(a));
}
__device__ __forceinline__ u64 pack2(float x) {
    u64 r; asm("mov.b64 %0, {%1, %1};" : "=l"(r) : "f"(x)); return r;
}
__device__ __forceinline__ float2 unpack2(u64 v) {
    float2 f; asm("mov.b64 {%0, %1}, %2;" : "=f"(f.x), "=f"(f.y) : "l"(v)); return f;
}
__device__ __forceinline__ u64 d2u(double d) { return __double_as_longlong(d); }
__device__ __forceinline__ int read_id(const void* p, int i, bool is64) {
    return is64 ? (int)((const long long*)p)[i] : ((const int*)p)[i];
}

// smem rows: 8 floats of payload padded to 12 (48B: 16B-aligned, bank-staggered)
#define RS 12

extern "C" __global__ void __launch_bounds__(NT, 2)
deepfm_kernel(P30 a, float* __restrict__ out, int B)
{
    __shared__ __align__(16) float sXT[77  * RS];
    __shared__ __align__(16) float sH1[256 * RS];
    __shared__ __align__(16) float sH2[128 * RS];
    __shared__ __align__(16) float sH3[64  * RS];
    __shared__ float sBase[TS];
    __shared__ float sPrice[TS];
    __shared__ int   sIdx[TS * 9];

    const int t  = threadIdx.x;
    const int w  = t >> 5;
    const int ln = t & 31;
    const int s0blk = blockIdx.x * TS;

    // ---- input-layout detection (deterministic, data-driven) ----
    const u64* u0 = (const u64*)a.p[0];
    const bool is64 = ((u0[0] | u0[1] | u0[2] | u0[3]) < (1ULL << 20));
    const u64* u7 = (const u64*)a.p[7];
    const bool dict = (u7[0] < (1ULL << 40));

    const void* idp[9];
    #pragma unroll
    for (int f = 0; f < 7; f++) idp[f] = a.p[f];
    const float* price;
    if (dict) { idp[7] = a.p[7]; idp[8] = a.p[8]; price = (const float*)a.p[9]; }
    else      { price = (const float*)a.p[7]; idp[7] = a.p[8]; idp[8] = a.p[9]; }

    const float* emb[9];
    #pragma unroll
    for (int f = 0; f < 9; f++) emb[f] = (const float*)a.p[10 + f];
    const float* __restrict__ w_dense = (const float*)a.p[19];
    const float* __restrict__ b_dense = (const float*)a.p[20];
    const float* __restrict__ fm_v    = (const float*)a.p[21];
    const float* __restrict__ W1 = (const float*)a.p[22];
    const float* __restrict__ b1 = (const float*)a.p[23];
    const float* __restrict__ W2 = (const float*)a.p[24];
    const float* __restrict__ b2 = (const float*)a.p[25];
    const float* __restrict__ W3 = (const float*)a.p[26];
    const float* __restrict__ b3 = (const float*)a.p[27];
    const float* __restrict__ Wo = (const float*)a.p[28];
    const float* __restrict__ bo = (const float*)a.p[29];

    // ---- gather ids + price ----
    if (t < TS * 9) {
        int s = t / 9, f = t - s * 9;
        sIdx[s * 9 + f] = read_id(idp[f], s0blk + s, is64);
    }
    if (t >= 96 && t < 96 + TS) sPrice[t - 96] = price[s0blk + (t - 96)];
    __syncthreads();

    // ---- warps 0-3: FM + dense (8 samples); warps 4-7: build XT[77][8] ----
    if (w < 4) {
        int s = w * 2 + (ln >> 4);
        int e = ln & 15;
        float pv = sPrice[s] * 1e-3f;
        float fs = 0.f, ss = 0.f;
        #pragma unroll
        for (int f = 0; f < 9; f++) {
            int row = c_FOFF[f] + sIdx[s * 9 + f];
            float v = fm_v[row * 16 + e];
            fs += v; ss += v * v;
        }
        {
            float v = fm_v[NF_LAST * 16 + e];
            fs += pv * v; ss += pv * pv * v * v;
        }
        float val = fs * fs - ss;
        #pragma unroll
        for (int o = 8; o; o >>= 1) val += __shfl_xor_sync(0xffffffffu, val, o, 16);
        float fm = 0.5f * val;

        float dn = 0.f;
        if (e < 9)  dn = w_dense[c_FOFF[e] + sIdx[s * 9 + e]];
        if (e == 9) dn = pv * w_dense[NF_LAST];
        #pragma unroll
        for (int o = 8; o; o >>= 1) dn += __shfl_xor_sync(0xffffffffu, dn, o, 16);

        if (e == 0) sBase[s] = fm + dn + b_dense[0];
    } else {
        for (int idx = t - 128; idx < TS * 77; idx += 128) {
            int s = idx & 7, c = idx >> 3;
            float v;
            if (c == 76) v = sPrice[s];
            else {
                int f = 8;
                #pragma unroll
                for (int k = 8; k >= 1; k--) if (c < c_EOFF[k]) f = k - 1;
                v = emb[f][sIdx[s * 9 + f] * c_EDIM[f] + (c - c_EOFF[f])];
            }
            sXT[c * RS + s] = v;
        }
    }
    __syncthreads();

    // ---- Layer 1: K=77, N=256. 8 warps x 32 outs. Thread: 2j x 4s. ----
    {
        int jgl = ln & 15, sg = ln >> 4;
        int j0 = (w * 16 + jgl) * 2;       // 0..510? no: w<8 -> 0..254
        int s0 = sg * 4;
        float2 bv = *(const float2*)(b1 + j0);
        u64 a00 = pack2(bv.x), a01 = a00;  // j0 : sample pairs (0,1),(2,3)
        u64 a10 = pack2(bv.y), a11 = a10;  // j0+1
        #pragma unroll 7
        for (int i = 0; i < 77; i++) {
            float2 wf = *(const float2*)(W1 + i * 256 + j0);
            double2 xv = *(const double2*)(sXT + i * RS + s0);
            u64 x01 = d2u(xv.x), x23 = d2u(xv.y);
            u64 w0 = pack2(wf.x), w1 = pack2(wf.y);
            ffma2(a00, w0, x01); ffma2(a01, w0, x23);
            ffma2(a10, w1, x01); ffma2(a11, w1, x23);
        }
        float2 f00 = unpack2(a00), f01 = unpack2(a01);
        float2 f10 = unpack2(a10), f11 = unpack2(a11);
        *(float4*)(sH1 + j0 * RS + s0) = make_float4(
            fmaxf(f00.x,0.f), fmaxf(f00.y,0.f), fmaxf(f01.x,0.f), fmaxf(f01.y,0.f));
        *(float4*)(sH1 + (j0 + 1) * RS + s0) = make_float4(
            fmaxf(f10.x,0.f), fmaxf(f10.y,0.f), fmaxf(f11.x,0.f), fmaxf(f11.y,0.f));
    }
    __syncthreads();

    // ---- Layer 2: K=256 (intra-warp split x2), N=128. Thread: 2j x 4s x K/2. ----
    {
        int jgl = ln & 7;
        int sg  = (ln >> 3) & 1;
        int ks  = ln >> 4;                 // K half
        int j0  = w * 16 + jgl * 2;        // 0..126
        int s0  = sg * 4;
        u64 a00 = 0, a01 = 0, a10 = 0, a11 = 0;
        const float* Wp = W2 + ks * 128 * 128 + j0;
        const float* Xp = sH1 + ks * 128 * RS + s0;
        #pragma unroll 8
        for (int ii = 0; ii < 128; ii++) {
            float2 wf = *(const float2*)(Wp + ii * 128);
            double2 xv = *(const double2*)(Xp + ii * RS);
            u64 x01 = d2u(xv.x), x23 = d2u(xv.y);
            u64 w0 = pack2(wf.x), w1 = pack2(wf.y);
            ffma2(a00, w0, x01); ffma2(a01, w0, x23);
            ffma2(a10, w1, x01); ffma2(a11, w1, x23);
        }
        // reduce across K halves (lanes ln ^ 16)
        a00 += 0; // keep compiler from reordering weirdly
        u64 r;
        r = __shfl_xor_sync(0xffffffffu, a00, 16); fadd2(a00, r);
        r = __shfl_xor_sync(0xffffffffu, a01, 16); fadd2(a01, r);
        r = __shfl_xor_sync(0xffffffffu, a10, 16); fadd2(a10, r);
        r = __shfl_xor_sync(0xffffffffu, a11, 16); fadd2(a11, r);
        if (ks == 0) {
            u64 bb0 = pack2(b2[j0]), bb1 = pack2(b2[j0 + 1]);
            fadd2(a00, bb0); fadd2(a01, bb0);
            fadd2(a10, bb1); fadd2(a11, bb1);
            float2 f00 = unpack2(a00), f01 = unpack2(a01);
            float2 f10 = unpack2(a10), f11 = unpack2(a11);
            *(float4*)(sH2 + j0 * RS + s0) = make_float4(
                fmaxf(f00.x,0.f), fmaxf(f00.y,0.f), fmaxf(f01.x,0.f), fmaxf(f01.y,0.f));
            *(float4*)(sH2 + (j0 + 1) * RS + s0) = make_float4(
                fmaxf(f10.x,0.f), fmaxf(f10.y,0.f), fmaxf(f11.x,0.f), fmaxf(f11.y,0.f));
        }
    }
    __syncthreads();

    // ---- Layer 3: K=128 (intra-warp split x4), N=64. Thread: 2j x 4s x K/4. ----
    {
        int jgl = ln & 3;
        int sg  = (ln >> 2) & 1;
        int ks  = ln >> 3;                 // K quarter
        int j0  = w * 8 + jgl * 2;         // 0..62
        int s0  = sg * 4;
        u64 a00 = 0, a01 = 0, a10 = 0, a11 = 0;
        const float* Wp = W3 + ks * 32 * 64 + j0;
        const float* Xp = sH2 + ks * 32 * RS + s0;
        #pragma unroll 8
        for (int ii = 0; ii < 32; ii++) {
            float2 wf = *(const float2*)(Wp + ii * 64);
            double2 xv = *(const double2*)(Xp + ii * RS);
            u64 x01 = d2u(xv.x), x23 = d2u(xv.y);
            u64 w0 = pack2(wf.x), w1 = pack2(wf.y);
            ffma2(a00, w0, x01); ffma2(a01, w0, x23);
            ffma2(a10, w1, x01); ffma2(a11, w1, x23);
        }
        u64 r;
        r = __shfl_xor_sync(0xffffffffu, a00, 8);  fadd2(a00, r);
        r = __shfl_xor_sync(0xffffffffu, a01, 8);  fadd2(a01, r);
        r = __shfl_xor_sync(0xffffffffu, a10, 8);  fadd2(a10, r);
        r = __shfl_xor_sync(0xffffffffu, a11, 8);  fadd2(a11, r);
        r = __shfl_xor_sync(0xffffffffu, a00, 16); fadd2(a00, r);
        r = __shfl_xor_sync(0xffffffffu, a01, 16); fadd2(a01, r);
        r = __shfl_xor_sync(0xffffffffu, a10, 16); fadd2(a10, r);
        r = __shfl_xor_sync(0xffffffffu, a11, 16); fadd2(a11, r);
        if (ks == 0) {
            u64 bb0 = pack2(b3[j0]), bb1 = pack2(b3[j0 + 1]);
            fadd2(a00, bb0); fadd2(a01, bb0);
            fadd2(a10, bb1); fadd2(a11, bb1);
            float2 f00 = unpack2(a00), f01 = unpack2(a01);
            float2 f10 = unpack2(a10), f11 = unpack2(a11);
            *(float4*)(sH3 + j0 * RS + s0) = make_float4(
                fmaxf(f00.x,0.f), fmaxf(f00.y,0.f), fmaxf(f01.x,0.f), fmaxf(f01.y,0.f));
            *(float4*)(sH3 + (j0 + 1) * RS + s0) = make_float4(
                fmaxf(f10.x,0.f), fmaxf(f10.y,0.f), fmaxf(f11.x,0.f), fmaxf(f11.y,0.f));
        }
    }
    __syncthreads();

    // ---- Output: warp 0. 4 lanes per sample, each sums 16 of 64. ----
    if (w == 0) {
        int s = ln >> 2;                   // 0..7
        int q = ln & 3;
        float v = 0.f;
        #pragma unroll
        for (int i = 0; i < 16; i++)
            v += sH3[(q * 16 + i) * RS + s] * Wo[q * 16 + i];
        v += __shfl_xor_sync(0xffffffffu, v, 2, 4);
        v += __shfl_xor_sync(0xffffffffu, v, 1, 4);
        if (q == 0 && s0blk + s < B)
            out[s0blk + s] = v + bo[0] + sBase[s];
    }
}

extern "C" void kernel_launch(void* const* d_in, const int* in_sizes, int n_in,
                              void* d_out, int out_size)
{
    (void)in_sizes; (void)n_in;
    P30 a;
    for (int i = 0; i < 30; i++) a.p[i] = d_in[i];
    deepfm_kernel<<<NBLK, NT>>>(a, (float*)d_out, out_size);
}